// round 8
// baseline (speedup 1.0000x reference)
#include <cuda_runtime.h>
#include <math.h>

#define NMAX 100000
#define EMAX 1600000
#define H 128
#define GG 64
#define BN_EPS 1e-5f
#define SCAN_B 1024

// ---------------- scratch (device globals: no allocation allowed) ----------
__device__ float g_h[NMAX * H];      // layer activations
__device__ float g_z[NMAX * H];      // GEMM output / attention hidden
__device__ float g_agg[NMAX * H];    // aggregation result
__device__ float g_dinv[NMAX];
__device__ float g_alog[NMAX];       // attention logits
__device__ float g_stats[2 * H];     // BN sum / sumsq
__device__ float g_part[256];        // reduction partials
__device__ float g_scal[4];          // [0]=gmax, [1]=1/sumexp
__device__ float g_pooled[GG * H];
__device__ float g_counts[GG];
__device__ int   g_idxmode;          // 0 = indices are int32, 1 = int64
__device__ int   g_E;                // edge count (computed on device)
__device__ float g_probe;            // diagnostic accumulator (0 when healthy)
// CSR build scratch
__device__ int g_cnt[NMAX];
__device__ int g_cur[NMAX];
__device__ int g_rexc[NMAX];
__device__ int g_bsum[SCAN_B];
__device__ int g_bsumx[SCAN_B];
__device__ int g_rowstart[NMAX + 1];
__device__ int g_col[EMAX];

// ---------------- diagnostics ------------------------------------------------
__global__ void k_zero_probe() { if (threadIdx.x == 0) g_probe = 0.0f; }

// which: 0=g_z 1=g_agg 2=g_h 3=g_alog 4=g_pooled 5=g_counts
__global__ void k_probe(int which, long long len, long long stride, float code) {
    __shared__ float sm[256];
    const float* a = (which == 0) ? g_z
                   : (which == 1) ? g_agg
                   : (which == 2) ? g_h
                   : (which == 3) ? g_alog
                   : (which == 4) ? g_pooled
                   : g_counts;
    float s = 0.0f;
    for (long long i = (long long)threadIdx.x * stride; i < len; i += 256LL * stride)
        s += fabsf(a[i]);
    sm[threadIdx.x] = s;
    __syncthreads();
    for (int st = 128; st; st >>= 1) {
        if (threadIdx.x < st) sm[threadIdx.x] += sm[threadIdx.x + st];
        __syncthreads();
    }
    if (threadIdx.x == 0 && sm[0] == 0.0f) atomicAdd(&g_probe, code);
}

// ---------------- dual-dtype index load ------------------------------------
__device__ __forceinline__ int ld_idx(const void* p, long long i) {
    if (g_idxmode) return (int)((const long long*)p)[i];
    return ((const int*)p)[i];
}

__global__ void k_detect(const long long* __restrict__ ei, int n,
                         long long raw, int bytes_mode, long long avail64) {
    int bad = 0;
    int m = (avail64 < 1024) ? (int)avail64 : 1024;
    if (m < 1) m = 1;
    for (int i = threadIdx.x; i < m; i += 32) {
        long long v = ei[i];
        if (v < 0 || v >= (long long)n) bad = 1;
    }
    unsigned anybad = __ballot_sync(0xffffffffu, bad);
    if (threadIdx.x == 0) {
        int mode = (anybad == 0u) ? 1 : 0;
        g_idxmode = mode;
        long long E;
        if (bytes_mode) E = raw / ((mode ? 8 : 4) * 2);
        else            E = raw / 2;
        if (E > EMAX) E = EMAX;
        g_E = (int)E;
    }
}

// ---------------- CSR build ------------------------------------------------
__global__ void k_zero_cnt(int n) {
    int i = blockIdx.x * blockDim.x + threadIdx.x;
    if (i < n) { g_cnt[i] = 0; g_cur[i] = 0; }
}

__global__ void k_hist(const void* __restrict__ ei, int n) {
    int i = blockIdx.x * blockDim.x + threadIdx.x;
    int E = g_E;
    if (i >= E) return;
    int d = ld_idx(ei, (long long)E + i);
    if ((unsigned)d < (unsigned)n) atomicAdd(&g_cnt[d], 1);
}

__global__ void k_dinv(int n) {
    int i = blockIdx.x * blockDim.x + threadIdx.x;
    if (i < n) g_dinv[i] = rsqrtf((float)(g_cnt[i] + 1));
}

__global__ void k_scan1(int n) {
    __shared__ int sm[SCAN_B];
    int i = blockIdx.x * SCAN_B + threadIdx.x;
    int v = (i < n) ? g_cnt[i] : 0;
    sm[threadIdx.x] = v;
    __syncthreads();
    for (int off = 1; off < SCAN_B; off <<= 1) {
        int t = (threadIdx.x >= off) ? sm[threadIdx.x - off] : 0;
        __syncthreads();
        sm[threadIdx.x] += t;
        __syncthreads();
    }
    if (i < n) g_rexc[i] = sm[threadIdx.x] - v;
    if (threadIdx.x == SCAN_B - 1) g_bsum[blockIdx.x] = sm[threadIdx.x];
}

__global__ void k_scan2(int nb) {
    __shared__ int sm[SCAN_B];
    int v = (threadIdx.x < nb) ? g_bsum[threadIdx.x] : 0;
    sm[threadIdx.x] = v;
    __syncthreads();
    for (int off = 1; off < SCAN_B; off <<= 1) {
        int t = (threadIdx.x >= off) ? sm[threadIdx.x - off] : 0;
        __syncthreads();
        sm[threadIdx.x] += t;
        __syncthreads();
    }
    g_bsumx[threadIdx.x] = sm[threadIdx.x] - v;
}

__global__ void k_scan3(int n) {
    int i = blockIdx.x * SCAN_B + threadIdx.x;
    if (i < n) g_rowstart[i] = g_rexc[i] + g_bsumx[i / SCAN_B];
    if (i == 0) g_rowstart[n] = g_E;
}

__global__ void k_fill(const void* __restrict__ ei, int n) {
    int e = blockIdx.x * blockDim.x + threadIdx.x;
    int E = g_E;
    if (e >= E) return;
    int s = ld_idx(ei, e);
    int d = ld_idx(ei, (long long)E + e);
    if ((unsigned)s >= (unsigned)n || (unsigned)d >= (unsigned)n) return;
    int pos = g_rowstart[d] + atomicAdd(&g_cur[d], 1);
    if (pos >= 0 && pos < EMAX) g_col[pos] = s;
}

// ---------------- small utility kernels ------------------------------------
__global__ void k_zero_stats() { g_stats[threadIdx.x] = 0.0f; }

__global__ void k_zero_pool() {
    int i = blockIdx.x * blockDim.x + threadIdx.x;
    if (i < GG * H) g_pooled[i] = 0.0f;
    if (i < GG) g_counts[i] = 0.0f;
}

// ---------------- SGEMM: g_z[n x 128] = A[n x 128] @ W[128 x 128] ----------
// SRC==0: A = Ain param (x).  SRC==1: A = g_h (device global, referenced in
// DEVICE code — passing __device__ symbols as host-side kernel args is the
// bug that broke rounds 1-7).
// EPI==0: C = A@W           EPI==1: C = tanh(A@W + bias)
template <int SRC, int EPI>
__global__ void k_gemm128(const float* __restrict__ Ain,
                          const float* __restrict__ W,
                          const float* __restrict__ bias, int nrows) {
    const float* A = (SRC == 0) ? Ain : (const float*)g_h;
    float* C = g_z;
    __shared__ float As[8][128];
    __shared__ float Bs[8][128];
    const int tid = threadIdx.x;
    const int tx = tid & 15;
    const int ty = tid >> 4;
    const int block_row = blockIdx.x * 128;

    const int a_r = tid >> 1;
    const int a_c = (tid & 1) * 4;
    const int b_r = tid >> 5;
    const int b_c = (tid & 31) * 4;

    float acc[8][8];
#pragma unroll
    for (int i = 0; i < 8; i++)
#pragma unroll
        for (int j = 0; j < 8; j++) acc[i][j] = 0.0f;

    for (int k0 = 0; k0 < 128; k0 += 8) {
        int gr = block_row + a_r;
        float4 av = make_float4(0.f, 0.f, 0.f, 0.f);
        if (gr < nrows) av = *(const float4*)(A + (size_t)gr * H + k0 + a_c);
        As[a_c + 0][a_r] = av.x;
        As[a_c + 1][a_r] = av.y;
        As[a_c + 2][a_r] = av.z;
        As[a_c + 3][a_r] = av.w;
        float4 bv = *(const float4*)(W + (size_t)(k0 + b_r) * H + b_c);
        *(float4*)&Bs[b_r][b_c] = bv;
        __syncthreads();

#pragma unroll
        for (int kk = 0; kk < 8; kk++) {
            float ar[8], br[8];
            *(float4*)&ar[0] = *(const float4*)&As[kk][ty * 8];
            *(float4*)&ar[4] = *(const float4*)&As[kk][ty * 8 + 4];
            *(float4*)&br[0] = *(const float4*)&Bs[kk][tx * 8];
            *(float4*)&br[4] = *(const float4*)&Bs[kk][tx * 8 + 4];
#pragma unroll
            for (int i = 0; i < 8; i++)
#pragma unroll
                for (int j = 0; j < 8; j++) acc[i][j] += ar[i] * br[j];
        }
        __syncthreads();
    }

#pragma unroll
    for (int i = 0; i < 8; i++) {
        int gr = block_row + ty * 8 + i;
        if (gr >= nrows) continue;
        float* crow = C + (size_t)gr * H + tx * 8;
#pragma unroll
        for (int jc = 0; jc < 2; jc++) {
            float4 v;
            v.x = acc[i][jc * 4 + 0];
            v.y = acc[i][jc * 4 + 1];
            v.z = acc[i][jc * 4 + 2];
            v.w = acc[i][jc * 4 + 3];
            if (EPI == 1) {
                int col = tx * 8 + jc * 4;
                v.x = tanhf(v.x + bias[col + 0]);
                v.y = tanhf(v.y + bias[col + 1]);
                v.z = tanhf(v.z + bias[col + 2]);
                v.w = tanhf(v.w + bias[col + 3]);
            }
            *(float4*)(crow + jc * 4) = v;
        }
    }
}

// ---------------- gather aggregation: warp per node -------------------------
__global__ void k_gather(const float* __restrict__ bias, int n) {
    int node = (blockIdx.x * blockDim.x + threadIdx.x) >> 5;
    int lane = threadIdx.x & 31;
    if (node >= n) return;
    int beg = g_rowstart[node];
    int end = g_rowstart[node + 1];
    float di = g_dinv[node];

    float4 acc = ((const float4*)(g_z + (size_t)node * H))[lane];  // self loop
    acc.x *= di; acc.y *= di; acc.z *= di; acc.w *= di;

    for (int e = beg; e < end; e++) {
        int s = g_col[e];
        float w = g_dinv[s];
        float4 v = ((const float4*)(g_z + (size_t)s * H))[lane];
        acc.x += w * v.x;
        acc.y += w * v.y;
        acc.z += w * v.z;
        acc.w += w * v.w;
    }
    float4 b = ((const float4*)bias)[lane];
    acc.x = acc.x * di + b.x;
    acc.y = acc.y * di + b.y;
    acc.z = acc.z * di + b.z;
    acc.w = acc.w * di + b.w;
    ((float4*)(g_agg + (size_t)node * H))[lane] = acc;
}

// ---------------- BN: per-feature sum / sumsq -------------------------------
__global__ void k_bn_reduce(int n) {
    int j = threadIdx.x;
    float s = 0.0f, q = 0.0f;
    for (int r = blockIdx.x; r < n; r += gridDim.x) {
        float v = g_agg[(size_t)r * H + j];
        s += v;
        q += v * v;
    }
    atomicAdd(&g_stats[j], s);
    atomicAdd(&g_stats[H + j], q);
}

__global__ void k_bn_apply(const float* __restrict__ gamma,
                           const float* __restrict__ beta, int n, int residual) {
    int idx = blockIdx.x * blockDim.x + threadIdx.x;
    if (idx >= n * H) return;
    int j = idx & (H - 1);
    float inv_n = 1.0f / (float)n;
    float mean = g_stats[j] * inv_n;
    float var = g_stats[H + j] * inv_n - mean * mean;
    float v = (g_agg[idx] - mean) * rsqrtf(var + BN_EPS) * gamma[j] + beta[j];
    v = fmaxf(v, 0.0f);
    if (residual) v += g_h[idx];
    g_h[idx] = v;
}

// ---------------- attention logit -------------------------------------------
__global__ void k_alogit(const float* __restrict__ w2,
                         const float* __restrict__ b2, int n) {
    int w = (blockIdx.x * blockDim.x + threadIdx.x) >> 5;
    int lane = threadIdx.x & 31;
    if (w >= n) return;
    float4 t = ((const float4*)(g_z + (size_t)w * H))[lane];
    float4 ww = ((const float4*)w2)[lane];
    float d = t.x * ww.x + t.y * ww.y + t.z * ww.z + t.w * ww.w;
#pragma unroll
    for (int o = 16; o; o >>= 1) d += __shfl_xor_sync(0xffffffffu, d, o);
    if (lane == 0) g_alog[w] = d + b2[0];
}

// ---------------- global softmax reductions ---------------------------------
__global__ void k_max_partial(int n) {
    __shared__ float sm[256];
    float m = -INFINITY;
    for (int i = blockIdx.x * blockDim.x + threadIdx.x; i < n;
         i += gridDim.x * blockDim.x)
        m = fmaxf(m, g_alog[i]);
    sm[threadIdx.x] = m;
    __syncthreads();
    for (int s = 128; s; s >>= 1) {
        if (threadIdx.x < s) sm[threadIdx.x] = fmaxf(sm[threadIdx.x], sm[threadIdx.x + s]);
        __syncthreads();
    }
    if (threadIdx.x == 0) g_part[blockIdx.x] = sm[0];
}

__global__ void k_max_final() {
    __shared__ float sm[256];
    sm[threadIdx.x] = g_part[threadIdx.x];
    __syncthreads();
    for (int s = 128; s; s >>= 1) {
        if (threadIdx.x < s) sm[threadIdx.x] = fmaxf(sm[threadIdx.x], sm[threadIdx.x + s]);
        __syncthreads();
    }
    if (threadIdx.x == 0) g_scal[0] = sm[0];
}

__global__ void k_sum_partial(int n) {
    __shared__ float sm[256];
    float gmax = g_scal[0];
    float s = 0.0f;
    for (int i = blockIdx.x * blockDim.x + threadIdx.x; i < n;
         i += gridDim.x * blockDim.x)
        s += expf(g_alog[i] - gmax);
    sm[threadIdx.x] = s;
    __syncthreads();
    for (int st = 128; st; st >>= 1) {
        if (threadIdx.x < st) sm[threadIdx.x] += sm[threadIdx.x + st];
        __syncthreads();
    }
    if (threadIdx.x == 0) g_part[blockIdx.x] = sm[0];
}

__global__ void k_sum_final() {
    __shared__ float sm[256];
    sm[threadIdx.x] = g_part[threadIdx.x];
    __syncthreads();
    for (int st = 128; st; st >>= 1) {
        if (threadIdx.x < st) sm[threadIdx.x] += sm[threadIdx.x + st];
        __syncthreads();
    }
    if (threadIdx.x == 0) g_scal[1] = 1.0f / sm[0];
}

// ---------------- weighted mean-pool: one warp per node ---------------------
__global__ void k_pool(const void* __restrict__ batch, int n) {
    int w = (blockIdx.x * blockDim.x + threadIdx.x) >> 5;
    int lane = threadIdx.x & 31;
    if (w >= n) return;
    float wgt = expf(g_alog[w] - g_scal[0]) * g_scal[1];
    int g = ld_idx(batch, w);
    if ((unsigned)g >= (unsigned)GG) return;
    float4 v = ((const float4*)(g_h + (size_t)w * H))[lane];
    float* p = g_pooled + (size_t)g * H + lane * 4;
    atomicAdd(p + 0, v.x * wgt);
    atomicAdd(p + 1, v.y * wgt);
    atomicAdd(p + 2, v.z * wgt);
    atomicAdd(p + 3, v.w * wgt);
    if (lane == 0) atomicAdd(&g_counts[g], 1.0f);
}

// ---------------- final MLP: one block per graph ----------------------------
__global__ void k_mlp(const float* __restrict__ w1, const float* __restrict__ b1,
                      const float* __restrict__ w2, const float* __restrict__ b2,
                      float* __restrict__ out) {
    int g = blockIdx.x;
    int j = threadIdx.x;
    __shared__ float p[H], t[H];
    float c = fmaxf(g_counts[g], 1.0f);
    p[j] = g_pooled[g * H + j] / c;
    __syncthreads();
    float acc = 0.0f;
#pragma unroll 8
    for (int k = 0; k < H; k++) acc += p[k] * w1[k * H + j];
    t[j] = fmaxf(acc + b1[j], 0.0f);
    __syncthreads();
    acc = 0.0f;
#pragma unroll 8
    for (int k = 0; k < H; k++) acc += t[k] * w2[k * H + j];
    out[g * H + j] = acc + b2[j] + g_probe;   // g_probe == 0 when healthy
}

// ---------------- host launcher ---------------------------------------------
extern "C" void kernel_launch(void* const* d_in, const int* in_sizes, int n_in,
                              void* d_out, int out_size) {
    // rank-based role inference (robust to elements|bytes, dict|alpha order)
    int ord[32];
    int m = n_in < 32 ? n_in : 32;
    for (int i = 0; i < m; i++) ord[i] = i;
    for (int i = 1; i < m; i++) {
        int key = ord[i];
        int ks = in_sizes[key];
        int j = i - 1;
        while (j >= 0 && in_sizes[ord[j]] < ks) { ord[j + 1] = ord[j]; j--; }
        ord[j + 1] = key;
    }

    const float* x      = (const float*)d_in[ord[0]];
    const void*  ei     = d_in[ord[1]];
    const void*  batch  = d_in[ord[2]];
    const float* conv_w = (const float*)d_in[ord[3]];
    const float* aw1    = (const float*)d_in[ord[4]];
    const float* pw1    = (const float*)d_in[ord[5]];
    const float* pw2    = (const float*)d_in[ord[6]];
    const float* conv_b = (const float*)d_in[ord[7]];
    const float* bn_g   = (const float*)d_in[ord[8]];
    const float* bn_b   = (const float*)d_in[ord[9]];
    const float* ab1    = (const float*)d_in[ord[10]];
    const float* aw2    = (const float*)d_in[ord[11]];
    const float* pb1    = (const float*)d_in[ord[12]];
    const float* pb2    = (const float*)d_in[ord[13]];
    const float* ab2    = (const float*)d_in[ord[14]];
    float* out = (float*)d_out;

    const int bytes_mode = (in_sizes[ord[14]] != 1) ? 1 : 0;
    const int fbytes = bytes_mode ? 4 : 1;

    const long long x_raw  = in_sizes[ord[0]];
    const long long ei_raw = in_sizes[ord[1]];
    const int n = (int)(x_raw / (H * fbytes));
    const long long E_ub = bytes_mode ? ei_raw / 8 : ei_raw / 2;
    const long long avail64 = (bytes_mode ? ei_raw : ei_raw * 4) / 8;

    const int T = 256;
    const int gb_n   = (n + T - 1) / T;
    const int gb_e   = (int)((E_ub + T - 1) / T);
    const int gb_nh  = (n * H + T - 1) / T;
    const int gb_nw  = (n * 32 + T - 1) / T;
    const int gb_gemm = (n + 127) / 128;
    const int nb_scan = (n + SCAN_B - 1) / SCAN_B;
    const long long nh = (long long)n * H;

    k_zero_probe<<<1, 32>>>();

    // ---- index dtype detection + CSR build + degree normalization ----
    k_detect<<<1, 32>>>((const long long*)ei, n, ei_raw, bytes_mode, avail64);
    k_zero_cnt<<<gb_n, T>>>(n);
    k_hist<<<gb_e, T>>>(ei, n);
    k_dinv<<<gb_n, T>>>(n);
    k_scan1<<<nb_scan, SCAN_B>>>(n);
    k_scan2<<<1, SCAN_B>>>(nb_scan);
    k_scan3<<<nb_scan, SCAN_B>>>(n);
    k_fill<<<gb_e, T>>>(ei, n);

    // ---- GCN layers ----
    for (int i = 0; i < 3; i++) {
        if (i == 0)
            k_gemm128<0, 0><<<gb_gemm, T>>>(x, conv_w, nullptr, n);
        else
            k_gemm128<1, 0><<<gb_gemm, T>>>(nullptr, conv_w + (size_t)i * H * H, nullptr, n);
        if (i == 0) k_probe<<<1, 256>>>(0, nh, 997, 1e9f);
        k_zero_stats<<<1, 256>>>();
        k_gather<<<gb_nw, T>>>(conv_b + (size_t)i * H, n);
        if (i == 0) k_probe<<<1, 256>>>(1, nh, 997, 1e8f);
        k_bn_reduce<<<1024, 128>>>(n);
        k_bn_apply<<<gb_nh, T>>>(bn_g + (size_t)i * H, bn_b + (size_t)i * H, n, i > 0);
        if (i == 0) k_probe<<<1, 256>>>(2, nh, 997, 1e7f);
    }

    // ---- attention ----
    k_gemm128<1, 1><<<gb_gemm, T>>>(nullptr, aw1, ab1, n);
    k_alogit<<<gb_nw, T>>>(aw2, ab2, n);
    k_probe<<<1, 256>>>(3, n, 1, 1e6f);
    k_max_partial<<<256, 256>>>(n);
    k_max_final<<<1, 256>>>();
    k_sum_partial<<<256, 256>>>(n);
    k_sum_final<<<1, 256>>>();

    // ---- pooling + MLP ----
    k_zero_pool<<<(GG * H + T - 1) / T, T>>>();
    k_pool<<<gb_nw, T>>>(batch, n);
    k_probe<<<1, 256>>>(4, GG * H, 1, 1e5f);
    k_probe<<<1, 256>>>(5, GG, 1, 1e4f);
    k_mlp<<<GG, H>>>(pw1, pb1, pw2, pb2, out);
}

// round 9
// speedup vs baseline: 1.0420x; 1.0420x over previous
#include <cuda_runtime.h>
#include <math.h>

#define NMAX 100000
#define EMAX 1600000
#define H 128
#define GG 64
#define BN_EPS 1e-5f
#define SCAN_B 1024

// ---------------- scratch ----------------------------------------------------
__device__ float g_h[NMAX * H];
__device__ float g_z[NMAX * H];
__device__ float g_agg[NMAX * H];
__device__ float g_dinv[NMAX];
__device__ float g_alog[NMAX];
__device__ float g_stats[2 * H];
__device__ float g_part[256];
__device__ float g_scal[4];
__device__ float g_pooled[GG * H];
__device__ float g_counts[GG];
__device__ int   g_idxmode;
__device__ int   g_E;
__device__ int g_cnt[NMAX];
__device__ int g_cur[NMAX];
__device__ int g_rexc[NMAX];
__device__ int g_bsum[SCAN_B];
__device__ int g_bsumx[SCAN_B];
__device__ int g_rowstart[NMAX + 1];
__device__ int g_col[EMAX];

// ---------------- dual-dtype index load -------------------------------------
__device__ __forceinline__ int ld_idx(const void* p, long long i) {
    if (g_idxmode) return (int)((const long long*)p)[i];
    return ((const int*)p)[i];
}

__global__ void k_detect(const long long* __restrict__ ei, int n,
                         long long raw, int bytes_mode, long long avail64) {
    int bad = 0;
    int m = (avail64 < 1024) ? (int)avail64 : 1024;
    if (m < 1) m = 1;
    for (int i = threadIdx.x; i < m; i += 32) {
        long long v = ei[i];
        if (v < 0 || v >= (long long)n) bad = 1;
    }
    unsigned anybad = __ballot_sync(0xffffffffu, bad);
    if (threadIdx.x == 0) {
        int mode = (anybad == 0u) ? 1 : 0;
        g_idxmode = mode;
        long long E;
        if (bytes_mode) E = raw / ((mode ? 8 : 4) * 2);
        else            E = raw / 2;
        if (E > EMAX) E = EMAX;
        g_E = (int)E;
    }
}

// ---------------- CSR build --------------------------------------------------
__global__ void k_zero_cnt(int n) {
    int i = blockIdx.x * blockDim.x + threadIdx.x;
    if (i < n) { g_cnt[i] = 0; g_cur[i] = 0; }
}

__global__ void k_hist(const void* __restrict__ ei, int n) {
    int i = blockIdx.x * blockDim.x + threadIdx.x;
    int E = g_E;
    if (i >= E) return;
    int d = ld_idx(ei, (long long)E + i);
    if ((unsigned)d < (unsigned)n) atomicAdd(&g_cnt[d], 1);
}

__global__ void k_scan1(int n) {   // also computes dinv
    __shared__ int sm[SCAN_B];
    int i = blockIdx.x * SCAN_B + threadIdx.x;
    int v = (i < n) ? g_cnt[i] : 0;
    if (i < n) g_dinv[i] = rsqrtf((float)(v + 1));   // +1 self loop
    sm[threadIdx.x] = v;
    __syncthreads();
    for (int off = 1; off < SCAN_B; off <<= 1) {
        int t = (threadIdx.x >= off) ? sm[threadIdx.x - off] : 0;
        __syncthreads();
        sm[threadIdx.x] += t;
        __syncthreads();
    }
    if (i < n) g_rexc[i] = sm[threadIdx.x] - v;
    if (threadIdx.x == SCAN_B - 1) g_bsum[blockIdx.x] = sm[threadIdx.x];
}

__global__ void k_scan2(int nb) {
    __shared__ int sm[SCAN_B];
    int v = (threadIdx.x < nb) ? g_bsum[threadIdx.x] : 0;
    sm[threadIdx.x] = v;
    __syncthreads();
    for (int off = 1; off < SCAN_B; off <<= 1) {
        int t = (threadIdx.x >= off) ? sm[threadIdx.x - off] : 0;
        __syncthreads();
        sm[threadIdx.x] += t;
        __syncthreads();
    }
    g_bsumx[threadIdx.x] = sm[threadIdx.x] - v;
}

__global__ void k_scan3(int n) {
    int i = blockIdx.x * SCAN_B + threadIdx.x;
    if (i < n) g_rowstart[i] = g_rexc[i] + g_bsumx[i / SCAN_B];
    if (i == 0) g_rowstart[n] = g_E;
}

__global__ void k_fill(const void* __restrict__ ei, int n) {
    int e = blockIdx.x * blockDim.x + threadIdx.x;
    int E = g_E;
    if (e >= E) return;
    int s = ld_idx(ei, e);
    int d = ld_idx(ei, (long long)E + e);
    if ((unsigned)s >= (unsigned)n || (unsigned)d >= (unsigned)n) return;
    int pos = g_rowstart[d] + atomicAdd(&g_cur[d], 1);
    if (pos >= 0 && pos < EMAX) g_col[pos] = s;
}

// ---------------- SGEMM with register prefetch -------------------------------
// g_z = A @ W.  SRC==0: A=Ain(x)  SRC==1: A=g_h.
// EPI==0: plain store to g_z.
// EPI==1 (attention): g_alog[row] = sum_col tanh(z+b1)[col]*w2[col] + b2 (no z store)
template <int SRC, int EPI>
__global__ void k_gemm128(const float* __restrict__ Ain,
                          const float* __restrict__ W,
                          const float* __restrict__ bias,
                          const float* __restrict__ w2,
                          const float* __restrict__ b2,
                          int nrows) {
    const float* A = (SRC == 0) ? Ain : (const float*)g_h;
    __shared__ float As[8][128];
    __shared__ float Bs[8][128];
    const int tid = threadIdx.x;
    const int tx = tid & 15;
    const int ty = tid >> 4;
    const int block_row = blockIdx.x * 128;

    const int a_r = tid >> 1;
    const int a_c = (tid & 1) * 4;
    const int b_r = tid >> 5;
    const int b_c = (tid & 31) * 4;

    const int gr_ld = block_row + a_r;
    const bool a_ok = gr_ld < nrows;
    const float* a_ptr = A + (size_t)gr_ld * H + a_c;
    const float* b_ptr = W + (size_t)b_r * H + b_c;

    float4 a_reg = a_ok ? *(const float4*)a_ptr : make_float4(0.f, 0.f, 0.f, 0.f);
    float4 b_reg = *(const float4*)b_ptr;

    float acc[8][8];
#pragma unroll
    for (int i = 0; i < 8; i++)
#pragma unroll
        for (int j = 0; j < 8; j++) acc[i][j] = 0.0f;

    for (int k0 = 0; k0 < 128; k0 += 8) {
        As[a_c + 0][a_r] = a_reg.x;
        As[a_c + 1][a_r] = a_reg.y;
        As[a_c + 2][a_r] = a_reg.z;
        As[a_c + 3][a_r] = a_reg.w;
        *(float4*)&Bs[b_r][b_c] = b_reg;
        __syncthreads();

        if (k0 + 8 < 128) {   // prefetch next tile during compute
            a_reg = a_ok ? *(const float4*)(a_ptr + k0 + 8)
                         : make_float4(0.f, 0.f, 0.f, 0.f);
            b_reg = *(const float4*)(b_ptr + (size_t)(k0 + 8) * H);
        }

#pragma unroll
        for (int kk = 0; kk < 8; kk++) {
            float ar[8], br[8];
            *(float4*)&ar[0] = *(const float4*)&As[kk][ty * 8];
            *(float4*)&ar[4] = *(const float4*)&As[kk][ty * 8 + 4];
            *(float4*)&br[0] = *(const float4*)&Bs[kk][tx * 8];
            *(float4*)&br[4] = *(const float4*)&Bs[kk][tx * 8 + 4];
#pragma unroll
            for (int i = 0; i < 8; i++)
#pragma unroll
                for (int j = 0; j < 8; j++) acc[i][j] += ar[i] * br[j];
        }
        __syncthreads();
    }

    if (EPI == 0) {
#pragma unroll
        for (int i = 0; i < 8; i++) {
            int gr = block_row + ty * 8 + i;
            if (gr >= nrows) continue;
            float* crow = g_z + (size_t)gr * H + tx * 8;
            float4 v0 = make_float4(acc[i][0], acc[i][1], acc[i][2], acc[i][3]);
            float4 v1 = make_float4(acc[i][4], acc[i][5], acc[i][6], acc[i][7]);
            *(float4*)(crow + 0) = v0;
            *(float4*)(crow + 4) = v1;
        }
    } else {
        float w2r[8], b1r[8];
#pragma unroll
        for (int j = 0; j < 8; j++) {
            w2r[j] = w2[tx * 8 + j];
            b1r[j] = bias[tx * 8 + j];
        }
        float b2v = b2[0];
#pragma unroll
        for (int i = 0; i < 8; i++) {
            float part = 0.0f;
#pragma unroll
            for (int j = 0; j < 8; j++)
                part += tanhf(acc[i][j] + b1r[j]) * w2r[j];
#pragma unroll
            for (int o = 1; o < 16; o <<= 1)
                part += __shfl_xor_sync(0xffffffffu, part, o);
            int gr = block_row + ty * 8 + i;
            if (tx == 0 && gr < nrows) g_alog[gr] = part + b2v;
        }
    }
}

// ---------------- gather aggregation: warp per node, batched indices --------
__global__ void k_gather(const float* __restrict__ bias, int n) {
    // fused: zero BN stats for the upcoming bn_reduce
    if (blockIdx.x == 0 && threadIdx.x < 256) g_stats[threadIdx.x] = 0.0f;

    int node = (blockIdx.x * blockDim.x + threadIdx.x) >> 5;
    int lane = threadIdx.x & 31;
    if (node >= n) return;
    int beg = g_rowstart[node];
    int end = g_rowstart[node + 1];
    float di = g_dinv[node];

    float4 acc = ((const float4*)(g_z + (size_t)node * H))[lane];  // self loop
    acc.x *= di; acc.y *= di; acc.z *= di; acc.w *= di;

    for (int base = beg; base < end; base += 32) {
        int idx = base + lane;
        int col = 0; float w = 0.0f;
        if (idx < end) { col = g_col[idx]; w = g_dinv[col]; }
        int cnt = end - base; if (cnt > 32) cnt = 32;
#pragma unroll 4
        for (int i = 0; i < cnt; i++) {
            int s = __shfl_sync(0xffffffffu, col, i);
            float ww = __shfl_sync(0xffffffffu, w, i);
            float4 v = ((const float4*)(g_z + (size_t)s * H))[lane];
            acc.x += ww * v.x;
            acc.y += ww * v.y;
            acc.z += ww * v.z;
            acc.w += ww * v.w;
        }
    }
    float4 b = ((const float4*)bias)[lane];
    acc.x = acc.x * di + b.x;
    acc.y = acc.y * di + b.y;
    acc.z = acc.z * di + b.z;
    acc.w = acc.w * di + b.w;
    ((float4*)(g_agg + (size_t)node * H))[lane] = acc;
}

// ---------------- BN ----------------------------------------------------------
__global__ void k_bn_reduce(int n) {
    int j = threadIdx.x;
    float s = 0.0f, q = 0.0f;
    for (int r = blockIdx.x; r < n; r += gridDim.x) {
        float v = g_agg[(size_t)r * H + j];
        s += v;
        q += v * v;
    }
    atomicAdd(&g_stats[j], s);
    atomicAdd(&g_stats[H + j], q);
}

__global__ void k_bn_apply(const float* __restrict__ gamma,
                           const float* __restrict__ beta, int n, int residual) {
    int idx = blockIdx.x * blockDim.x + threadIdx.x;
    if (idx >= n * H) return;
    int j = idx & (H - 1);
    float inv_n = 1.0f / (float)n;
    float mean = g_stats[j] * inv_n;
    float var = g_stats[H + j] * inv_n - mean * mean;
    float v = (g_agg[idx] - mean) * rsqrtf(var + BN_EPS) * gamma[j] + beta[j];
    v = fmaxf(v, 0.0f);
    if (residual) v += g_h[idx];
    g_h[idx] = v;
}

// ---------------- global softmax reductions -----------------------------------
__global__ void k_max_partial(int n) {
    __shared__ float sm[256];
    float m = -INFINITY;
    for (int i = blockIdx.x * blockDim.x + threadIdx.x; i < n;
         i += gridDim.x * blockDim.x)
        m = fmaxf(m, g_alog[i]);
    sm[threadIdx.x] = m;
    __syncthreads();
    for (int s = 128; s; s >>= 1) {
        if (threadIdx.x < s) sm[threadIdx.x] = fmaxf(sm[threadIdx.x], sm[threadIdx.x + s]);
        __syncthreads();
    }
    if (threadIdx.x == 0) g_part[blockIdx.x] = sm[0];
}

__global__ void k_max_final() {
    __shared__ float sm[256];
    sm[threadIdx.x] = g_part[threadIdx.x];
    __syncthreads();
    for (int s = 128; s; s >>= 1) {
        if (threadIdx.x < s) sm[threadIdx.x] = fmaxf(sm[threadIdx.x], sm[threadIdx.x + s]);
        __syncthreads();
    }
    if (threadIdx.x == 0) g_scal[0] = sm[0];
}

__global__ void k_sum_partial(int n) {
    __shared__ float sm[256];
    float gmax = g_scal[0];
    float s = 0.0f;
    for (int i = blockIdx.x * blockDim.x + threadIdx.x; i < n;
         i += gridDim.x * blockDim.x)
        s += expf(g_alog[i] - gmax);
    sm[threadIdx.x] = s;
    __syncthreads();
    for (int st = 128; st; st >>= 1) {
        if (threadIdx.x < st) sm[threadIdx.x] += sm[threadIdx.x + st];
        __syncthreads();
    }
    if (threadIdx.x == 0) g_part[blockIdx.x] = sm[0];
}

__global__ void k_sum_final() {   // also zeroes pool accumulators
    __shared__ float sm[256];
    sm[threadIdx.x] = g_part[threadIdx.x];
    for (int i = threadIdx.x; i < GG * H; i += 256) g_pooled[i] = 0.0f;
    if (threadIdx.x < GG) g_counts[threadIdx.x] = 0.0f;
    __syncthreads();
    for (int st = 128; st; st >>= 1) {
        if (threadIdx.x < st) sm[threadIdx.x] += sm[threadIdx.x + st];
        __syncthreads();
    }
    if (threadIdx.x == 0) g_scal[1] = 1.0f / sm[0];
}

// ---------------- weighted mean-pool -------------------------------------------
__global__ void k_pool(const void* __restrict__ batch, int n) {
    int w = (blockIdx.x * blockDim.x + threadIdx.x) >> 5;
    int lane = threadIdx.x & 31;
    if (w >= n) return;
    float wgt = expf(g_alog[w] - g_scal[0]) * g_scal[1];
    int g = ld_idx(batch, w);
    if ((unsigned)g >= (unsigned)GG) return;
    float4 v = ((const float4*)(g_h + (size_t)w * H))[lane];
    float* p = g_pooled + (size_t)g * H + lane * 4;
    atomicAdd(p + 0, v.x * wgt);
    atomicAdd(p + 1, v.y * wgt);
    atomicAdd(p + 2, v.z * wgt);
    atomicAdd(p + 3, v.w * wgt);
    if (lane == 0) atomicAdd(&g_counts[g], 1.0f);
}

// ---------------- final MLP ------------------------------------------------------
__global__ void k_mlp(const float* __restrict__ w1, const float* __restrict__ b1,
                      const float* __restrict__ w2, const float* __restrict__ b2,
                      float* __restrict__ out) {
    int g = blockIdx.x;
    int j = threadIdx.x;
    __shared__ float p[H], t[H];
    float c = fmaxf(g_counts[g], 1.0f);
    p[j] = g_pooled[g * H + j] / c;
    __syncthreads();
    float acc = 0.0f;
#pragma unroll 8
    for (int k = 0; k < H; k++) acc += p[k] * w1[k * H + j];
    t[j] = fmaxf(acc + b1[j], 0.0f);
    __syncthreads();
    acc = 0.0f;
#pragma unroll 8
    for (int k = 0; k < H; k++) acc += t[k] * w2[k * H + j];
    out[g * H + j] = acc + b2[j];
}

// ---------------- host launcher ----------------------------------------------
extern "C" void kernel_launch(void* const* d_in, const int* in_sizes, int n_in,
                              void* d_out, int out_size) {
    int ord[32];
    int m = n_in < 32 ? n_in : 32;
    for (int i = 0; i < m; i++) ord[i] = i;
    for (int i = 1; i < m; i++) {
        int key = ord[i];
        int ks = in_sizes[key];
        int j = i - 1;
        while (j >= 0 && in_sizes[ord[j]] < ks) { ord[j + 1] = ord[j]; j--; }
        ord[j + 1] = key;
    }

    const float* x      = (const float*)d_in[ord[0]];
    const void*  ei     = d_in[ord[1]];
    const void*  batch  = d_in[ord[2]];
    const float* conv_w = (const float*)d_in[ord[3]];
    const float* aw1    = (const float*)d_in[ord[4]];
    const float* pw1    = (const float*)d_in[ord[5]];
    const float* pw2    = (const float*)d_in[ord[6]];
    const float* conv_b = (const float*)d_in[ord[7]];
    const float* bn_g   = (const float*)d_in[ord[8]];
    const float* bn_b   = (const float*)d_in[ord[9]];
    const float* ab1    = (const float*)d_in[ord[10]];
    const float* aw2    = (const float*)d_in[ord[11]];
    const float* pb1    = (const float*)d_in[ord[12]];
    const float* pb2    = (const float*)d_in[ord[13]];
    const float* ab2    = (const float*)d_in[ord[14]];
    float* out = (float*)d_out;

    const int bytes_mode = (in_sizes[ord[14]] != 1) ? 1 : 0;
    const int fbytes = bytes_mode ? 4 : 1;

    const long long x_raw  = in_sizes[ord[0]];
    const long long ei_raw = in_sizes[ord[1]];
    const int n = (int)(x_raw / (H * fbytes));
    const long long E_ub = bytes_mode ? ei_raw / 8 : ei_raw / 2;
    const long long avail64 = (bytes_mode ? ei_raw : ei_raw * 4) / 8;

    const int T = 256;
    const int gb_n   = (n + T - 1) / T;
    const int gb_e   = (int)((E_ub + T - 1) / T);
    const int gb_nh  = (n * H + T - 1) / T;
    const int gb_nw  = (n * 32 + T - 1) / T;
    const int gb_gemm = (n + 127) / 128;
    const int nb_scan = (n + SCAN_B - 1) / SCAN_B;

    // ---- index detection + CSR build ----
    k_detect<<<1, 32>>>((const long long*)ei, n, ei_raw, bytes_mode, avail64);
    k_zero_cnt<<<gb_n, T>>>(n);
    k_hist<<<gb_e, T>>>(ei, n);
    k_scan1<<<nb_scan, SCAN_B>>>(n);
    k_scan2<<<1, SCAN_B>>>(nb_scan);
    k_scan3<<<nb_scan, SCAN_B>>>(n);
    k_fill<<<gb_e, T>>>(ei, n);

    // ---- GCN layers ----
    for (int i = 0; i < 3; i++) {
        if (i == 0)
            k_gemm128<0, 0><<<gb_gemm, T>>>(x, conv_w, nullptr, nullptr, nullptr, n);
        else
            k_gemm128<1, 0><<<gb_gemm, T>>>(nullptr, conv_w + (size_t)i * H * H,
                                            nullptr, nullptr, nullptr, n);
        k_gather<<<gb_nw, T>>>(conv_b + (size_t)i * H, n);
        k_bn_reduce<<<1024, 128>>>(n);
        k_bn_apply<<<gb_nh, T>>>(bn_g + (size_t)i * H, bn_b + (size_t)i * H, n, i > 0);
    }

    // ---- attention (fused logit epilogue) ----
    k_gemm128<1, 1><<<gb_gemm, T>>>(nullptr, aw1, ab1, aw2, ab2, n);
    k_max_partial<<<256, 256>>>(n);
    k_max_final<<<1, 256>>>();
    k_sum_partial<<<256, 256>>>(n);
    k_sum_final<<<1, 256>>>();

    // ---- pooling + MLP ----
    k_pool<<<gb_nw, T>>>(batch, n);
    k_mlp<<<GG, H>>>(pw1, pb1, pw2, pb2, out);
}